// round 5
// baseline (speedup 1.0000x reference)
#include <cuda_runtime.h>
#include <cuda_bf16.h>
#include <cstdint>

#define NROWS 8192
#define KDIM  256
#define CDIM  256      // H*O
#define NHEAD 4
#define ODIM  64
#define NB    512      // concat B cols: [weight | proj_w^T]
#define MAXE  2048

// ---------------- device scratch (no allocation allowed) ----------------
__device__ float g_B[KDIM * NB];            // 512 KB
__device__ float g_support[NROWS * CDIM];   // 8 MB
__device__ float g_f1[NHEAD * NROWS];       // 128 KB
__device__ float g_f2[NHEAD * NROWS];       // 128 KB

// ---------------- kernel 0: pack B = [weight | proj_w^T] ----------------
__global__ void pack_b_kernel(const float* __restrict__ weight,
                              const float* __restrict__ proj_w) {
    int idx = blockIdx.x * 256 + threadIdx.x;     // 0 .. 256*512-1
    int k = idx >> 9;
    int c = idx & 511;
    float v = (c < 256) ? weight[k * 256 + c]
                        : proj_w[(c - 256) * 256 + k];
    g_B[idx] = v;
}

// ---------------- kernel 1: GEMM [8192,256] x [256,512] ----------------
// cols 0..255  -> g_support
// cols 256..511-> d_out = proj + proj_b + bias   (base for attention add)
__global__ void gemm_kernel(const float* __restrict__ A,
                            const float* __restrict__ bias,
                            const float* __restrict__ proj_b,
                            float* __restrict__ out) {
    __shared__ float As[64][17];
    __shared__ float Bs[16][64];
    const int tx = threadIdx.x, ty = threadIdx.y;
    const int tid = ty * 16 + tx;
    const int row0 = blockIdx.y * 64;
    const int col0 = blockIdx.x * 64;

    float acc[4][4] = {};

    for (int k0 = 0; k0 < KDIM; k0 += 16) {
        // load A tile 64x16
        #pragma unroll
        for (int l = 0; l < 4; l++) {
            int e = tid + l * 256;
            int r = e >> 4, kk = e & 15;
            As[r][kk] = A[(size_t)(row0 + r) * KDIM + k0 + kk];
        }
        // load B tile 16x64 (float4)
        {
            int kk = tid >> 4;
            int n4 = (tid & 15) * 4;
            float4 b = *(const float4*)&g_B[(size_t)(k0 + kk) * NB + col0 + n4];
            *(float4*)&Bs[kk][n4] = b;
        }
        __syncthreads();
        #pragma unroll
        for (int k = 0; k < 16; k++) {
            float a[4];
            #pragma unroll
            for (int i = 0; i < 4; i++) a[i] = As[ty * 4 + i][k];
            float4 bv = *(float4*)&Bs[k][tx * 4];
            float bb[4] = {bv.x, bv.y, bv.z, bv.w};
            #pragma unroll
            for (int i = 0; i < 4; i++)
                #pragma unroll
                for (int j = 0; j < 4; j++)
                    acc[i][j] += a[i] * bb[j];
        }
        __syncthreads();
    }

    #pragma unroll
    for (int i = 0; i < 4; i++) {
        int r = row0 + ty * 4 + i;
        #pragma unroll
        for (int j = 0; j < 4; j++) {
            int cg = col0 + tx * 4 + j;
            float v = acc[i][j];
            if (cg < 256) {
                g_support[(size_t)r * CDIM + cg] = v;
            } else {
                int cc = cg - 256;
                out[(size_t)r * CDIM + cc] = v + bias[cc] + proj_b[cc];
            }
        }
    }
}

// ---------------- kernel 2: f1/f2 per-head dots (warp per row) ----------------
__global__ void f1f2_kernel(const float* __restrict__ wu,
                            const float* __restrict__ wv) {
    int gwarp = (blockIdx.x * blockDim.x + threadIdx.x) >> 5;
    int lane = threadIdx.x & 31;
    if (gwarp >= NROWS) return;
    const float* row = g_support + (size_t)gwarp * CDIM;

    float u[NHEAD], v[NHEAD];
    #pragma unroll
    for (int h = 0; h < NHEAD; h++) { u[h] = 0.f; v[h] = 0.f; }

    #pragma unroll
    for (int w8 = 0; w8 < 8; w8++) {
        const int h = w8 >> 1;                 // head is uniform per chunk
        int c = w8 * 32 + lane;
        int o = c & 63;
        float s = row[c];
        u[h] += s * wu[h * 64 + o];
        v[h] += s * wv[h * 64 + o];
    }
    #pragma unroll
    for (int h = 0; h < NHEAD; h++) {
        #pragma unroll
        for (int off = 16; off; off >>= 1) {
            u[h] += __shfl_xor_sync(0xFFFFFFFFu, u[h], off);
            v[h] += __shfl_xor_sync(0xFFFFFFFFu, v[h], off);
        }
    }
    if (lane == 0) {
        #pragma unroll
        for (int h = 0; h < NHEAD; h++) {
            g_f1[h * NROWS + gwarp] = u[h];
            g_f2[h * NROWS + gwarp] = v[h];
        }
    }
}

// ---------------- kernel 3: per-row sparse softmax + aggregation ----------------
// block = one row i, 256 threads
__global__ void attn_kernel(const float* __restrict__ adj,
                            float* __restrict__ out) {
    __shared__ int   s_cols[MAXE];
    __shared__ float s_p[NHEAD][MAXE];
    __shared__ int   s_cnt;
    __shared__ float s_red[NHEAD][8];

    const int i = blockIdx.x;
    const int tid = threadIdx.x;
    const int lane = tid & 31;
    const int warp = tid >> 5;

    if (tid == 0) s_cnt = 0;
    __syncthreads();

    // ---- phase 1: gather nonzero columns of row i ----
    const float* arow = adj + (size_t)i * NROWS;
    for (int c = tid; c < NROWS; c += 256) {
        if (arow[c] != 0.0f) {
            int pos = atomicAdd(&s_cnt, 1);
            if (pos < MAXE) s_cols[pos] = c;
        }
    }
    __syncthreads();
    const int cnt = min(s_cnt, MAXE);

    float f2h[NHEAD];
    #pragma unroll
    for (int h = 0; h < NHEAD; h++) f2h[h] = g_f2[h * NROWS + i];

    // ---- phase 2: leaky-relu logits + per-head max ----
    float mx[NHEAD] = {-1e30f, -1e30f, -1e30f, -1e30f};
    for (int e = tid; e < cnt; e += 256) {
        int j = s_cols[e];
        #pragma unroll
        for (int h = 0; h < NHEAD; h++) {
            float s = g_f1[h * NROWS + j] + f2h[h];
            s = (s > 0.f) ? s : 0.2f * s;
            s_p[h][e] = s;
            mx[h] = fmaxf(mx[h], s);
        }
    }
    #pragma unroll
    for (int h = 0; h < NHEAD; h++)
        #pragma unroll
        for (int off = 16; off; off >>= 1)
            mx[h] = fmaxf(mx[h], __shfl_xor_sync(0xFFFFFFFFu, mx[h], off));
    if (lane == 0)
        #pragma unroll
        for (int h = 0; h < NHEAD; h++) s_red[h][warp] = mx[h];
    __syncthreads();

    float M[NHEAD];
    #pragma unroll
    for (int h = 0; h < NHEAD; h++) {
        float m = -1e30f;
        #pragma unroll
        for (int w = 0; w < 8; w++) m = fmaxf(m, s_red[h][w]);
        M[h] = m;
    }
    __syncthreads();  // before s_red reuse

    // ---- phase 3: exp + per-head sums ----
    float sm[NHEAD] = {0.f, 0.f, 0.f, 0.f};
    for (int e = tid; e < cnt; e += 256) {
        #pragma unroll
        for (int h = 0; h < NHEAD; h++) {
            float p = __expf(s_p[h][e] - M[h]);
            s_p[h][e] = p;
            sm[h] += p;
        }
    }
    #pragma unroll
    for (int h = 0; h < NHEAD; h++)
        #pragma unroll
        for (int off = 16; off; off >>= 1)
            sm[h] += __shfl_xor_sync(0xFFFFFFFFu, sm[h], off);
    if (lane == 0)
        #pragma unroll
        for (int h = 0; h < NHEAD; h++) s_red[h][warp] = sm[h];
    __syncthreads();

    const int c = tid;
    const int h = c >> 6;
    float D = 0.f;
    #pragma unroll
    for (int w = 0; w < 8; w++) D += s_red[h][w];
    const float inv = (D > 0.f) ? (1.0f / D) : 0.f;

    // ---- phase 4: accumulate out[i, c] = base + (sum_e p * support[j,c]) / D ----
    float acc0 = 0.f, acc1 = 0.f, acc2 = 0.f, acc3 = 0.f;
    int e = 0;
    for (; e + 4 <= cnt; e += 4) {
        int j0 = s_cols[e + 0], j1 = s_cols[e + 1];
        int j2 = s_cols[e + 2], j3 = s_cols[e + 3];
        float p0 = s_p[h][e + 0], p1 = s_p[h][e + 1];
        float p2 = s_p[h][e + 2], p3 = s_p[h][e + 3];
        acc0 += p0 * g_support[(size_t)j0 * CDIM + c];
        acc1 += p1 * g_support[(size_t)j1 * CDIM + c];
        acc2 += p2 * g_support[(size_t)j2 * CDIM + c];
        acc3 += p3 * g_support[(size_t)j3 * CDIM + c];
    }
    for (; e < cnt; e++) {
        acc0 += s_p[h][e] * g_support[(size_t)s_cols[e] * CDIM + c];
    }
    float acc = (acc0 + acc1) + (acc2 + acc3);
    out[(size_t)i * CDIM + c] += acc * inv;
}

// ---------------- launch ----------------
extern "C" void kernel_launch(void* const* d_in, const int* in_sizes, int n_in,
                              void* d_out, int out_size) {
    const float* inputs  = (const float*)d_in[0];  // [8192,256]
    const float* adj     = (const float*)d_in[1];  // [8192,8192]
    const float* weight  = (const float*)d_in[2];  // [256,256]
    const float* wu      = (const float*)d_in[3];  // [4,64,1]
    const float* wv      = (const float*)d_in[4];  // [4,64,1]
    const float* bias    = (const float*)d_in[5];  // [1,256]
    const float* proj_w  = (const float*)d_in[6];  // [256,256]
    const float* proj_b  = (const float*)d_in[7];  // [256]
    float* out = (float*)d_out;                    // [8192,256]

    pack_b_kernel<<<(KDIM * NB) / 256, 256>>>(weight, proj_w);

    dim3 gblk(16, 16);
    dim3 ggrid(NB / 64, NROWS / 64);
    gemm_kernel<<<ggrid, gblk>>>(inputs, bias, proj_b, out);

    f1f2_kernel<<<NROWS / 8, 256>>>(wu, wv);

    attn_kernel<<<NROWS, 256>>>(adj, out);
}

// round 6
// speedup vs baseline: 1.4743x; 1.4743x over previous
#include <cuda_runtime.h>
#include <cuda_bf16.h>
#include <cstdint>

#define NROWS 8192
#define KDIM  256
#define CDIM  256      // H*O
#define NHEAD 4
#define ODIM  64
#define NB    512      // concat B cols: [weight | proj_w^T]
#define MAXE  1024     // max edges per row (mean ~410, 30-sigma safe)

// ---------------- device scratch (no allocation allowed) ----------------
__device__ float  g_B[KDIM * NB];            // 512 KB
__device__ float  g_support[NROWS * CDIM];   // 8 MB
__device__ float4 g_f1v[NROWS];              // 128 KB (4 heads packed)
__device__ float4 g_f2v[NROWS];              // 128 KB

// ---------------- kernel 0: pack B = [weight | proj_w^T] ----------------
__global__ void pack_b_kernel(const float* __restrict__ weight,
                              const float* __restrict__ proj_w) {
    int idx = blockIdx.x * 256 + threadIdx.x;     // 0 .. 256*512-1
    int k = idx >> 9;
    int c = idx & 511;
    float v = (c < 256) ? weight[k * 256 + c]
                        : proj_w[(c - 256) * 256 + k];
    g_B[idx] = v;
}

// ---------------- kernel 1: GEMM [8192,256] x [256,512] ----------------
// cols 0..255  -> g_support
// cols 256..511-> d_out = proj + proj_b + bias   (base for attention add)
__global__ void gemm_kernel(const float* __restrict__ A,
                            const float* __restrict__ bias,
                            const float* __restrict__ proj_b,
                            float* __restrict__ out) {
    __shared__ float As[64][17];
    __shared__ float Bs[16][64];
    const int tx = threadIdx.x, ty = threadIdx.y;
    const int tid = ty * 16 + tx;
    const int row0 = blockIdx.y * 64;
    const int col0 = blockIdx.x * 64;

    float acc[4][4] = {};

    for (int k0 = 0; k0 < KDIM; k0 += 16) {
        #pragma unroll
        for (int l = 0; l < 4; l++) {
            int e = tid + l * 256;
            int r = e >> 4, kk = e & 15;
            As[r][kk] = A[(size_t)(row0 + r) * KDIM + k0 + kk];
        }
        {
            int kk = tid >> 4;
            int n4 = (tid & 15) * 4;
            float4 b = *(const float4*)&g_B[(size_t)(k0 + kk) * NB + col0 + n4];
            *(float4*)&Bs[kk][n4] = b;
        }
        __syncthreads();
        #pragma unroll
        for (int k = 0; k < 16; k++) {
            float a[4];
            #pragma unroll
            for (int i = 0; i < 4; i++) a[i] = As[ty * 4 + i][k];
            float4 bv = *(float4*)&Bs[k][tx * 4];
            float bb[4] = {bv.x, bv.y, bv.z, bv.w};
            #pragma unroll
            for (int i = 0; i < 4; i++)
                #pragma unroll
                for (int j = 0; j < 4; j++)
                    acc[i][j] += a[i] * bb[j];
        }
        __syncthreads();
    }

    #pragma unroll
    for (int i = 0; i < 4; i++) {
        int r = row0 + ty * 4 + i;
        #pragma unroll
        for (int j = 0; j < 4; j++) {
            int cg = col0 + tx * 4 + j;
            float v = acc[i][j];
            if (cg < 256) {
                g_support[(size_t)r * CDIM + cg] = v;
            } else {
                int cc = cg - 256;
                out[(size_t)r * CDIM + cc] = v + bias[cc] + proj_b[cc];
            }
        }
    }
}

// ---------------- kernel 2: f1/f2 per-head dots (warp per row, packed out) ----
__global__ void f1f2_kernel(const float* __restrict__ wu,
                            const float* __restrict__ wv) {
    int gwarp = (blockIdx.x * blockDim.x + threadIdx.x) >> 5;
    int lane = threadIdx.x & 31;
    if (gwarp >= NROWS) return;
    const float* row = g_support + (size_t)gwarp * CDIM;

    float u[NHEAD] = {0.f, 0.f, 0.f, 0.f};
    float v[NHEAD] = {0.f, 0.f, 0.f, 0.f};

    #pragma unroll
    for (int w8 = 0; w8 < 8; w8++) {
        const int h = w8 >> 1;
        int c = w8 * 32 + lane;
        int o = c & 63;
        float s = row[c];
        u[h] += s * wu[h * 64 + o];
        v[h] += s * wv[h * 64 + o];
    }
    #pragma unroll
    for (int h = 0; h < NHEAD; h++) {
        #pragma unroll
        for (int off = 16; off; off >>= 1) {
            u[h] += __shfl_xor_sync(0xFFFFFFFFu, u[h], off);
            v[h] += __shfl_xor_sync(0xFFFFFFFFu, v[h], off);
        }
    }
    if (lane == 0) {
        g_f1v[gwarp] = make_float4(u[0], u[1], u[2], u[3]);
        g_f2v[gwarp] = make_float4(v[0], v[1], v[2], v[3]);
    }
}

// ---------------- kernel 3: per-row sparse softmax + aggregation ----------------
// block = one row i, 256 threads. Vectorized float4 everywhere.
__global__ void __launch_bounds__(256)
attn_kernel(const float* __restrict__ adj, float* __restrict__ out) {
    __shared__ int    s_cols[MAXE];
    __shared__ float  s_p[MAXE * NHEAD];     // [e][h] packed
    __shared__ float4 s_part[4][64];         // per-group partial sums
    __shared__ float  s_red[NHEAD][8];
    __shared__ float  s_inv[NHEAD];
    __shared__ int    s_cnt;

    const int i = blockIdx.x;
    const int tid = threadIdx.x;
    const int lane = tid & 31;
    const int warp = tid >> 5;

    if (tid == 0) s_cnt = 0;
    __syncthreads();

    // ---- phase 1: gather nonzero columns (float4 reads, ballot compaction) ----
    const float4* arow = (const float4*)(adj + (size_t)i * NROWS);
    const unsigned ltmask = (1u << lane) - 1u;
    #pragma unroll
    for (int it = 0; it < 8; it++) {
        int idx4 = it * 256 + tid;          // coalesced float4 index
        float4 v = arow[idx4];
        bool n0 = v.x != 0.f, n1 = v.y != 0.f, n2 = v.z != 0.f, n3 = v.w != 0.f;
        unsigned b0 = __ballot_sync(0xFFFFFFFFu, n0);
        unsigned b1 = __ballot_sync(0xFFFFFFFFu, n1);
        unsigned b2 = __ballot_sync(0xFFFFFFFFu, n2);
        unsigned b3 = __ballot_sync(0xFFFFFFFFu, n3);
        int tot = __popc(b0) + __popc(b1) + __popc(b2) + __popc(b3);
        int base = 0;
        if (lane == 0 && tot) base = atomicAdd(&s_cnt, tot);
        base = __shfl_sync(0xFFFFFFFFu, base, 0);
        int c0 = idx4 * 4;
        int p0 = base + __popc(b0 & ltmask);
        int p1 = base + __popc(b0) + __popc(b1 & ltmask);
        int p2 = base + __popc(b0) + __popc(b1) + __popc(b2 & ltmask);
        int p3 = base + __popc(b0) + __popc(b1) + __popc(b2) + __popc(b3 & ltmask);
        if (n0 && p0 < MAXE) s_cols[p0] = c0;
        if (n1 && p1 < MAXE) s_cols[p1] = c0 + 1;
        if (n2 && p2 < MAXE) s_cols[p2] = c0 + 2;
        if (n3 && p3 < MAXE) s_cols[p3] = c0 + 3;
    }
    __syncthreads();
    const int cnt = min(s_cnt, MAXE);

    // ---- phase 2 (fused): lrelu + exp (no max pass; logits bounded ~|20|) ----
    const float4 f2h = g_f2v[i];
    float4 sm = make_float4(0.f, 0.f, 0.f, 0.f);
    for (int e = tid; e < cnt; e += 256) {
        int j = s_cols[e];
        float4 f1 = __ldg(&g_f1v[j]);
        float sx = f1.x + f2h.x; sx = (sx > 0.f) ? sx : 0.2f * sx;
        float sy = f1.y + f2h.y; sy = (sy > 0.f) ? sy : 0.2f * sy;
        float sz = f1.z + f2h.z; sz = (sz > 0.f) ? sz : 0.2f * sz;
        float sw = f1.w + f2h.w; sw = (sw > 0.f) ? sw : 0.2f * sw;
        float px = __expf(sx), py = __expf(sy), pz = __expf(sz), pw = __expf(sw);
        ((float4*)s_p)[e] = make_float4(px, py, pz, pw);
        sm.x += px; sm.y += py; sm.z += pz; sm.w += pw;
    }
    #pragma unroll
    for (int off = 16; off; off >>= 1) {
        sm.x += __shfl_xor_sync(0xFFFFFFFFu, sm.x, off);
        sm.y += __shfl_xor_sync(0xFFFFFFFFu, sm.y, off);
        sm.z += __shfl_xor_sync(0xFFFFFFFFu, sm.z, off);
        sm.w += __shfl_xor_sync(0xFFFFFFFFu, sm.w, off);
    }
    if (lane == 0) {
        s_red[0][warp] = sm.x; s_red[1][warp] = sm.y;
        s_red[2][warp] = sm.z; s_red[3][warp] = sm.w;
    }
    __syncthreads();
    if (tid < NHEAD) {
        float D = 0.f;
        #pragma unroll
        for (int w = 0; w < 8; w++) D += s_red[tid][w];
        s_inv[tid] = (D > 0.f) ? (1.0f / D) : 0.f;
    }
    __syncthreads();

    // ---- phase 3: 4 edge-groups x 64 threads, float4 channels ----
    const int g = tid >> 6;       // edge phase 0..3
    const int t = tid & 63;       // channel group: channels [4t, 4t+4)
    const int h = t >> 4;         // head for these channels
    const float4* sup = (const float4*)g_support;

    float4 acc  = make_float4(0.f, 0.f, 0.f, 0.f);
    float4 acc2 = make_float4(0.f, 0.f, 0.f, 0.f);
    int e = g;
    for (; e + 4 < cnt; e += 8) {
        int j0 = s_cols[e];
        int j1 = s_cols[e + 4];
        float p0 = s_p[e * 4 + h];
        float p1 = s_p[(e + 4) * 4 + h];
        float4 v0 = sup[(size_t)j0 * 64 + t];
        float4 v1 = sup[(size_t)j1 * 64 + t];
        acc.x  += p0 * v0.x; acc.y  += p0 * v0.y; acc.z  += p0 * v0.z; acc.w  += p0 * v0.w;
        acc2.x += p1 * v1.x; acc2.y += p1 * v1.y; acc2.z += p1 * v1.z; acc2.w += p1 * v1.w;
    }
    if (e < cnt) {
        int j0 = s_cols[e];
        float p0 = s_p[e * 4 + h];
        float4 v0 = sup[(size_t)j0 * 64 + t];
        acc.x += p0 * v0.x; acc.y += p0 * v0.y; acc.z += p0 * v0.z; acc.w += p0 * v0.w;
    }
    acc.x += acc2.x; acc.y += acc2.y; acc.z += acc2.z; acc.w += acc2.w;
    s_part[g][t] = acc;
    __syncthreads();

    // ---- phase 4: combine groups, normalize, add base, store float4 ----
    if (tid < 64) {
        float inv = s_inv[tid >> 4];
        float4 a0 = s_part[0][tid];
        float4 a1 = s_part[1][tid];
        float4 a2 = s_part[2][tid];
        float4 a3 = s_part[3][tid];
        float4* o = (float4*)(out + (size_t)i * CDIM);
        float4 b = o[tid];
        b.x += ((a0.x + a1.x) + (a2.x + a3.x)) * inv;
        b.y += ((a0.y + a1.y) + (a2.y + a3.y)) * inv;
        b.z += ((a0.z + a1.z) + (a2.z + a3.z)) * inv;
        b.w += ((a0.w + a1.w) + (a2.w + a3.w)) * inv;
        o[tid] = b;
    }
}

// ---------------- launch ----------------
extern "C" void kernel_launch(void* const* d_in, const int* in_sizes, int n_in,
                              void* d_out, int out_size) {
    const float* inputs  = (const float*)d_in[0];  // [8192,256]
    const float* adj     = (const float*)d_in[1];  // [8192,8192]
    const float* weight  = (const float*)d_in[2];  // [256,256]
    const float* wu      = (const float*)d_in[3];  // [4,64,1]
    const float* wv      = (const float*)d_in[4];  // [4,64,1]
    const float* bias    = (const float*)d_in[5];  // [1,256]
    const float* proj_w  = (const float*)d_in[6];  // [256,256]
    const float* proj_b  = (const float*)d_in[7];  // [256]
    float* out = (float*)d_out;                    // [8192,256]

    pack_b_kernel<<<(KDIM * NB) / 256, 256>>>(weight, proj_w);

    dim3 gblk(16, 16);
    dim3 ggrid(NB / 64, NROWS / 64);
    gemm_kernel<<<ggrid, gblk>>>(inputs, bias, proj_b, out);

    f1f2_kernel<<<NROWS / 8, 256>>>(wu, wv);

    attn_kernel<<<NROWS, 256>>>(adj, out);
}

// round 7
// speedup vs baseline: 1.8423x; 1.2496x over previous
#include <cuda_runtime.h>
#include <cuda_bf16.h>
#include <cuda_fp16.h>
#include <cstdint>

#define NROWS 8192
#define KDIM  256
#define CDIM  256      // H*O
#define NHEAD 4
#define ODIM  64
#define NB    512      // concat B cols: [weight | proj_w^T]
#define MAXE  1024     // max edges per row (mean ~410, 30-sigma safe)

// ---------------- device scratch (no allocation allowed) ----------------
__device__ float   g_B[KDIM * NB];             // 512 KB
__device__ float   g_support[NROWS * CDIM];    // 8 MB (fp32, for f1/f2)
__device__ __half2 g_supp_h[NROWS * (CDIM/2)]; // 4 MB (fp16, for aggregation)
__device__ float4  g_f1v[NROWS];               // 128 KB (4 heads packed)
__device__ float4  g_f2v[NROWS];               // 128 KB

// ---------------- kernel 0: pack B = [weight | proj_w^T] ----------------
__global__ void pack_b_kernel(const float* __restrict__ weight,
                              const float* __restrict__ proj_w) {
    int idx = blockIdx.x * 256 + threadIdx.x;     // 0 .. 256*512-1
    int k = idx >> 9;
    int c = idx & 511;
    float v = (c < 256) ? weight[k * 256 + c]
                        : proj_w[(c - 256) * 256 + k];
    g_B[idx] = v;
}

// ---------------- kernel 1: GEMM [8192,256] x [256,512] ----------------
// cols 0..255  -> g_support (fp32) + g_supp_h (fp16)
// cols 256..511-> d_out = proj + proj_b + bias   (base for attention add)
__global__ void gemm_kernel(const float* __restrict__ A,
                            const float* __restrict__ bias,
                            const float* __restrict__ proj_b,
                            float* __restrict__ out) {
    __shared__ float As[64][17];
    __shared__ float Bs[16][64];
    const int tx = threadIdx.x, ty = threadIdx.y;
    const int tid = ty * 16 + tx;
    const int row0 = blockIdx.y * 64;
    const int col0 = blockIdx.x * 64;

    float acc[4][4] = {};

    for (int k0 = 0; k0 < KDIM; k0 += 16) {
        #pragma unroll
        for (int l = 0; l < 4; l++) {
            int e = tid + l * 256;
            int r = e >> 4, kk = e & 15;
            As[r][kk] = A[(size_t)(row0 + r) * KDIM + k0 + kk];
        }
        {
            int kk = tid >> 4;
            int n4 = (tid & 15) * 4;
            float4 b = *(const float4*)&g_B[(size_t)(k0 + kk) * NB + col0 + n4];
            *(float4*)&Bs[kk][n4] = b;
        }
        __syncthreads();
        #pragma unroll
        for (int k = 0; k < 16; k++) {
            float a[4];
            #pragma unroll
            for (int i = 0; i < 4; i++) a[i] = As[ty * 4 + i][k];
            float4 bv = *(float4*)&Bs[k][tx * 4];
            float bb[4] = {bv.x, bv.y, bv.z, bv.w};
            #pragma unroll
            for (int i = 0; i < 4; i++)
                #pragma unroll
                for (int j = 0; j < 4; j++)
                    acc[i][j] += a[i] * bb[j];
        }
        __syncthreads();
    }

    #pragma unroll
    for (int i = 0; i < 4; i++) {
        int r = row0 + ty * 4 + i;
        int cg0 = col0 + tx * 4;
        if (cg0 < 256) {
            // fp32 store
            *(float4*)&g_support[(size_t)r * CDIM + cg0] =
                make_float4(acc[i][0], acc[i][1], acc[i][2], acc[i][3]);
            // fp16 store (2x half2)
            __half2 h0 = __float22half2_rn(make_float2(acc[i][0], acc[i][1]));
            __half2 h1 = __float22half2_rn(make_float2(acc[i][2], acc[i][3]));
            g_supp_h[(size_t)r * (CDIM/2) + (cg0 >> 1)]     = h0;
            g_supp_h[(size_t)r * (CDIM/2) + (cg0 >> 1) + 1] = h1;
        } else {
            #pragma unroll
            for (int j = 0; j < 4; j++) {
                int cc = cg0 + j - 256;
                out[(size_t)r * CDIM + cc] = acc[i][j] + bias[cc] + proj_b[cc];
            }
        }
    }
}

// ---------------- kernel 2: f1/f2 per-head dots (warp per row, packed out) ----
__global__ void f1f2_kernel(const float* __restrict__ wu,
                            const float* __restrict__ wv) {
    int gwarp = (blockIdx.x * blockDim.x + threadIdx.x) >> 5;
    int lane = threadIdx.x & 31;
    if (gwarp >= NROWS) return;
    const float* row = g_support + (size_t)gwarp * CDIM;

    float u[NHEAD] = {0.f, 0.f, 0.f, 0.f};
    float v[NHEAD] = {0.f, 0.f, 0.f, 0.f};

    #pragma unroll
    for (int w8 = 0; w8 < 8; w8++) {
        const int h = w8 >> 1;
        int c = w8 * 32 + lane;
        int o = c & 63;
        float s = row[c];
        u[h] += s * wu[h * 64 + o];
        v[h] += s * wv[h * 64 + o];
    }
    #pragma unroll
    for (int h = 0; h < NHEAD; h++) {
        #pragma unroll
        for (int off = 16; off; off >>= 1) {
            u[h] += __shfl_xor_sync(0xFFFFFFFFu, u[h], off);
            v[h] += __shfl_xor_sync(0xFFFFFFFFu, v[h], off);
        }
    }
    if (lane == 0) {
        g_f1v[gwarp] = make_float4(u[0], u[1], u[2], u[3]);
        g_f2v[gwarp] = make_float4(v[0], v[1], v[2], v[3]);
    }
}

// ---------------- kernel 3: per-row sparse softmax + aggregation ----------------
// block = one row i, 256 threads.
// Phase 3: 8 edge-groups x 32 threads; each thread owns 8 channels (one LDG.128
// of 8 fp16 values per edge).
__global__ void __launch_bounds__(256)
attn_kernel(const float* __restrict__ adj, float* __restrict__ out) {
    __shared__ int    s_cols[MAXE];
    __shared__ float  s_p[MAXE * NHEAD];     // [e][h] packed
    __shared__ float  s_part[8][32][9];      // [group][thread][8ch + pad]
    __shared__ float  s_red[NHEAD][8];
    __shared__ float  s_inv[NHEAD];
    __shared__ int    s_cnt;

    const int i = blockIdx.x;
    const int tid = threadIdx.x;
    const int lane = tid & 31;
    const int warp = tid >> 5;

    if (tid == 0) s_cnt = 0;
    __syncthreads();

    // ---- phase 1: gather nonzero columns (float4 reads, ballot compaction) ----
    const float4* arow = (const float4*)(adj + (size_t)i * NROWS);
    const unsigned ltmask = (1u << lane) - 1u;
    #pragma unroll
    for (int it = 0; it < 8; it++) {
        int idx4 = it * 256 + tid;          // coalesced float4 index
        float4 v = arow[idx4];
        bool n0 = v.x != 0.f, n1 = v.y != 0.f, n2 = v.z != 0.f, n3 = v.w != 0.f;
        unsigned b0 = __ballot_sync(0xFFFFFFFFu, n0);
        unsigned b1 = __ballot_sync(0xFFFFFFFFu, n1);
        unsigned b2 = __ballot_sync(0xFFFFFFFFu, n2);
        unsigned b3 = __ballot_sync(0xFFFFFFFFu, n3);
        int tot = __popc(b0) + __popc(b1) + __popc(b2) + __popc(b3);
        int base = 0;
        if (lane == 0 && tot) base = atomicAdd(&s_cnt, tot);
        base = __shfl_sync(0xFFFFFFFFu, base, 0);
        int c0 = idx4 * 4;
        int p0 = base + __popc(b0 & ltmask);
        int p1 = base + __popc(b0) + __popc(b1 & ltmask);
        int p2 = base + __popc(b0) + __popc(b1) + __popc(b2 & ltmask);
        int p3 = base + __popc(b0) + __popc(b1) + __popc(b2) + __popc(b3 & ltmask);
        if (n0 && p0 < MAXE) s_cols[p0] = c0;
        if (n1 && p1 < MAXE) s_cols[p1] = c0 + 1;
        if (n2 && p2 < MAXE) s_cols[p2] = c0 + 2;
        if (n3 && p3 < MAXE) s_cols[p3] = c0 + 3;
    }
    __syncthreads();
    const int cnt = min(s_cnt, MAXE);

    // ---- phase 2 (fused): lrelu + exp (no max pass; logits bounded ~|20|) ----
    const float4 f2h = g_f2v[i];
    float4 sm = make_float4(0.f, 0.f, 0.f, 0.f);
    for (int e = tid; e < cnt; e += 256) {
        int j = s_cols[e];
        float4 f1 = __ldg(&g_f1v[j]);
        float sx = f1.x + f2h.x; sx = (sx > 0.f) ? sx : 0.2f * sx;
        float sy = f1.y + f2h.y; sy = (sy > 0.f) ? sy : 0.2f * sy;
        float sz = f1.z + f2h.z; sz = (sz > 0.f) ? sz : 0.2f * sz;
        float sw = f1.w + f2h.w; sw = (sw > 0.f) ? sw : 0.2f * sw;
        float px = __expf(sx), py = __expf(sy), pz = __expf(sz), pw = __expf(sw);
        ((float4*)s_p)[e] = make_float4(px, py, pz, pw);
        sm.x += px; sm.y += py; sm.z += pz; sm.w += pw;
    }
    #pragma unroll
    for (int off = 16; off; off >>= 1) {
        sm.x += __shfl_xor_sync(0xFFFFFFFFu, sm.x, off);
        sm.y += __shfl_xor_sync(0xFFFFFFFFu, sm.y, off);
        sm.z += __shfl_xor_sync(0xFFFFFFFFu, sm.z, off);
        sm.w += __shfl_xor_sync(0xFFFFFFFFu, sm.w, off);
    }
    if (lane == 0) {
        s_red[0][warp] = sm.x; s_red[1][warp] = sm.y;
        s_red[2][warp] = sm.z; s_red[3][warp] = sm.w;
    }
    __syncthreads();
    if (tid < NHEAD) {
        float D = 0.f;
        #pragma unroll
        for (int w = 0; w < 8; w++) D += s_red[tid][w];
        s_inv[tid] = (D > 0.f) ? (1.0f / D) : 0.f;
    }
    __syncthreads();

    // ---- phase 3: 8 edge-groups x 32 threads, 8 fp16 channels per thread ----
    const int g = warp;           // edge phase 0..7
    const int t = lane;           // channels [8t, 8t+8)
    const int h = t >> 3;         // head for these channels (uniform per thread)
    const uint4* suph = (const uint4*)g_supp_h;   // row stride = 32 uint4

    float acc[8] = {};
    float acc2[8] = {};
    int e = g;
    for (; e + 8 < cnt; e += 16) {
        int j0 = s_cols[e];
        int j1 = s_cols[e + 8];
        float p0 = s_p[e * 4 + h];
        float p1 = s_p[(e + 8) * 4 + h];
        uint4 v0 = suph[(size_t)j0 * 32 + t];
        uint4 v1 = suph[(size_t)j1 * 32 + t];
        float2 f00 = __half22float2(*(const __half2*)&v0.x);
        float2 f01 = __half22float2(*(const __half2*)&v0.y);
        float2 f02 = __half22float2(*(const __half2*)&v0.z);
        float2 f03 = __half22float2(*(const __half2*)&v0.w);
        acc[0] += p0 * f00.x; acc[1] += p0 * f00.y;
        acc[2] += p0 * f01.x; acc[3] += p0 * f01.y;
        acc[4] += p0 * f02.x; acc[5] += p0 * f02.y;
        acc[6] += p0 * f03.x; acc[7] += p0 * f03.y;
        float2 f10 = __half22float2(*(const __half2*)&v1.x);
        float2 f11 = __half22float2(*(const __half2*)&v1.y);
        float2 f12 = __half22float2(*(const __half2*)&v1.z);
        float2 f13 = __half22float2(*(const __half2*)&v1.w);
        acc2[0] += p1 * f10.x; acc2[1] += p1 * f10.y;
        acc2[2] += p1 * f11.x; acc2[3] += p1 * f11.y;
        acc2[4] += p1 * f12.x; acc2[5] += p1 * f12.y;
        acc2[6] += p1 * f13.x; acc2[7] += p1 * f13.y;
    }
    if (e < cnt) {
        int j0 = s_cols[e];
        float p0 = s_p[e * 4 + h];
        uint4 v0 = suph[(size_t)j0 * 32 + t];
        float2 f00 = __half22float2(*(const __half2*)&v0.x);
        float2 f01 = __half22float2(*(const __half2*)&v0.y);
        float2 f02 = __half22float2(*(const __half2*)&v0.z);
        float2 f03 = __half22float2(*(const __half2*)&v0.w);
        acc[0] += p0 * f00.x; acc[1] += p0 * f00.y;
        acc[2] += p0 * f01.x; acc[3] += p0 * f01.y;
        acc[4] += p0 * f02.x; acc[5] += p0 * f02.y;
        acc[6] += p0 * f03.x; acc[7] += p0 * f03.y;
    }
    #pragma unroll
    for (int k = 0; k < 8; k++) s_part[g][t][k] = acc[k] + acc2[k];
    __syncthreads();

    // ---- phase 4: combine 8 groups, normalize, add base, store ----
    if (tid < 32) {
        const float inv = s_inv[tid >> 3];
        float r[8] = {};
        #pragma unroll
        for (int gg = 0; gg < 8; gg++)
            #pragma unroll
            for (int k = 0; k < 8; k++)
                r[k] += s_part[gg][tid][k];
        float4* o = (float4*)(out + (size_t)i * CDIM);
        float4 b0 = o[tid * 2];
        float4 b1 = o[tid * 2 + 1];
        b0.x += r[0] * inv; b0.y += r[1] * inv; b0.z += r[2] * inv; b0.w += r[3] * inv;
        b1.x += r[4] * inv; b1.y += r[5] * inv; b1.z += r[6] * inv; b1.w += r[7] * inv;
        o[tid * 2]     = b0;
        o[tid * 2 + 1] = b1;
    }
}

// ---------------- launch ----------------
extern "C" void kernel_launch(void* const* d_in, const int* in_sizes, int n_in,
                              void* d_out, int out_size) {
    const float* inputs  = (const float*)d_in[0];  // [8192,256]
    const float* adj     = (const float*)d_in[1];  // [8192,8192]
    const float* weight  = (const float*)d_in[2];  // [256,256]
    const float* wu      = (const float*)d_in[3];  // [4,64,1]
    const float* wv      = (const float*)d_in[4];  // [4,64,1]
    const float* bias    = (const float*)d_in[5];  // [1,256]
    const float* proj_w  = (const float*)d_in[6];  // [256,256]
    const float* proj_b  = (const float*)d_in[7];  // [256]
    float* out = (float*)d_out;                    // [8192,256]

    pack_b_kernel<<<(KDIM * NB) / 256, 256>>>(weight, proj_w);

    dim3 gblk(16, 16);
    dim3 ggrid(NB / 64, NROWS / 64);
    gemm_kernel<<<ggrid, gblk>>>(inputs, bias, proj_b, out);

    f1f2_kernel<<<NROWS / 8, 256>>>(wu, wv);

    attn_kernel<<<NROWS, 256>>>(adj, out);
}

// round 8
// speedup vs baseline: 2.0227x; 1.0979x over previous
#include <cuda_runtime.h>
#include <cuda_bf16.h>
#include <cuda_fp16.h>
#include <cstdint>

#define NROWS 8192
#define KDIM  256
#define CDIM  256      // H*O
#define NHEAD 4
#define ODIM  64
#define NB    512      // concat B cols: [weight | proj_w^T]
#define MAXE  1024     // max edges per row (mean ~410, 30-sigma safe)
#define LN256 5.5451774444795624f

// ---------------- device scratch (no allocation allowed) ----------------
__device__ float   g_B[KDIM * NB];             // 512 KB
__device__ float   g_support[NROWS * CDIM];    // 8 MB (fp32, for f1/f2)
__device__ __half2 g_supp_h[NROWS * (CDIM/2)]; // 4 MB (fp16, for aggregation)
__device__ float4  g_f1v[NROWS];               // 128 KB (4 heads packed)
__device__ float4  g_f2v[NROWS];               // 128 KB
__device__ int     g_maxf1i[NHEAD];            // global per-head max of f1 (bits)

// ---------------- kernel 0: pack B = [weight | proj_w^T] ----------------
__global__ void pack_b_kernel(const float* __restrict__ weight,
                              const float* __restrict__ proj_w) {
    int idx = blockIdx.x * 256 + threadIdx.x;     // 0 .. 256*512-1
    if (idx < NHEAD) g_maxf1i[idx] = 0;           // 0.0f bits (bound only needs >= max)
    int k = idx >> 9;
    int c = idx & 511;
    float v = (c < 256) ? weight[k * 256 + c]
                        : proj_w[(c - 256) * 256 + k];
    g_B[idx] = v;
}

// ---------------- kernel 1: GEMM [8192,256] x [256,512] ----------------
// cols 0..255  -> g_support (fp32) + g_supp_h (fp16)
// cols 256..511-> d_out = proj + proj_b + bias   (base for attention add)
__global__ void gemm_kernel(const float* __restrict__ A,
                            const float* __restrict__ bias,
                            const float* __restrict__ proj_b,
                            float* __restrict__ out) {
    __shared__ float As[64][17];
    __shared__ float Bs[16][64];
    const int tx = threadIdx.x, ty = threadIdx.y;
    const int tid = ty * 16 + tx;
    const int row0 = blockIdx.y * 64;
    const int col0 = blockIdx.x * 64;

    float acc[4][4] = {};

    for (int k0 = 0; k0 < KDIM; k0 += 16) {
        #pragma unroll
        for (int l = 0; l < 4; l++) {
            int e = tid + l * 256;
            int r = e >> 4, kk = e & 15;
            As[r][kk] = A[(size_t)(row0 + r) * KDIM + k0 + kk];
        }
        {
            int kk = tid >> 4;
            int n4 = (tid & 15) * 4;
            float4 b = *(const float4*)&g_B[(size_t)(k0 + kk) * NB + col0 + n4];
            *(float4*)&Bs[kk][n4] = b;
        }
        __syncthreads();
        #pragma unroll
        for (int k = 0; k < 16; k++) {
            float a[4];
            #pragma unroll
            for (int i = 0; i < 4; i++) a[i] = As[ty * 4 + i][k];
            float4 bv = *(float4*)&Bs[k][tx * 4];
            float bb[4] = {bv.x, bv.y, bv.z, bv.w};
            #pragma unroll
            for (int i = 0; i < 4; i++)
                #pragma unroll
                for (int j = 0; j < 4; j++)
                    acc[i][j] += a[i] * bb[j];
        }
        __syncthreads();
    }

    #pragma unroll
    for (int i = 0; i < 4; i++) {
        int r = row0 + ty * 4 + i;
        int cg0 = col0 + tx * 4;
        if (cg0 < 256) {
            *(float4*)&g_support[(size_t)r * CDIM + cg0] =
                make_float4(acc[i][0], acc[i][1], acc[i][2], acc[i][3]);
            __half2 h0 = __float22half2_rn(make_float2(acc[i][0], acc[i][1]));
            __half2 h1 = __float22half2_rn(make_float2(acc[i][2], acc[i][3]));
            g_supp_h[(size_t)r * (CDIM/2) + (cg0 >> 1)]     = h0;
            g_supp_h[(size_t)r * (CDIM/2) + (cg0 >> 1) + 1] = h1;
        } else {
            #pragma unroll
            for (int j = 0; j < 4; j++) {
                int cc = cg0 + j - 256;
                out[(size_t)r * CDIM + cc] = acc[i][j] + bias[cc] + proj_b[cc];
            }
        }
    }
}

// ---------------- kernel 2: f1/f2 per-head dots + global f1 max ----------------
__global__ void f1f2_kernel(const float* __restrict__ wu,
                            const float* __restrict__ wv) {
    __shared__ float s_bm[NHEAD][8];
    int gwarp = (blockIdx.x * blockDim.x + threadIdx.x) >> 5;
    int lane = threadIdx.x & 31;
    int warp = (threadIdx.x >> 5);
    if (gwarp < NROWS) {
        const float* row = g_support + (size_t)gwarp * CDIM;

        float u[NHEAD] = {0.f, 0.f, 0.f, 0.f};
        float v[NHEAD] = {0.f, 0.f, 0.f, 0.f};

        #pragma unroll
        for (int w8 = 0; w8 < 8; w8++) {
            const int h = w8 >> 1;
            int c = w8 * 32 + lane;
            int o = c & 63;
            float s = row[c];
            u[h] += s * wu[h * 64 + o];
            v[h] += s * wv[h * 64 + o];
        }
        #pragma unroll
        for (int h = 0; h < NHEAD; h++) {
            #pragma unroll
            for (int off = 16; off; off >>= 1) {
                u[h] += __shfl_xor_sync(0xFFFFFFFFu, u[h], off);
                v[h] += __shfl_xor_sync(0xFFFFFFFFu, v[h], off);
            }
        }
        if (lane == 0) {
            g_f1v[gwarp] = make_float4(u[0], u[1], u[2], u[3]);
            g_f2v[gwarp] = make_float4(v[0], v[1], v[2], v[3]);
            #pragma unroll
            for (int h = 0; h < NHEAD; h++) s_bm[h][warp] = u[h];
        }
    } else if (lane == 0) {
        #pragma unroll
        for (int h = 0; h < NHEAD; h++) s_bm[h][warp] = 0.f;
    }
    __syncthreads();
    // one atomicMax per head per block (positive floats: int compare works)
    if (threadIdx.x < NHEAD) {
        float m = 0.f;
        #pragma unroll
        for (int w = 0; w < 8; w++) m = fmaxf(m, s_bm[threadIdx.x][w]);
        if (m > 0.f) atomicMax(&g_maxf1i[threadIdx.x], __float_as_int(m));
    }
}

// ---------------- kernel 3: per-row sparse softmax + aggregation ----------------
// block = one row i, 256 threads.
// Phase 3: 8 edge-groups x 32 threads; HFMA2 into half2 accumulators,
// p stored as half scaled by 256*exp(-Mhat) so it fits fp16 range.
__global__ void __launch_bounds__(256)
attn_kernel(const float* __restrict__ adj, float* __restrict__ out) {
    __shared__ int     s_cols[MAXE];
    __shared__ __half2 s_p2[MAXE * 2];       // [e][4 heads as 2x half2]
    __shared__ float   s_part[8][32][9];     // [group][thread][8ch + pad]
    __shared__ float   s_red[NHEAD][8];
    __shared__ float   s_inv[NHEAD];
    __shared__ int     s_cnt;

    const int i = blockIdx.x;
    const int tid = threadIdx.x;
    const int lane = tid & 31;
    const int warp = tid >> 5;

    if (tid == 0) s_cnt = 0;
    __syncthreads();

    // ---- phase 1: gather nonzero columns (float4 reads, ballot compaction) ----
    const float4* arow = (const float4*)(adj + (size_t)i * NROWS);
    const unsigned ltmask = (1u << lane) - 1u;
    #pragma unroll
    for (int it = 0; it < 8; it++) {
        int idx4 = it * 256 + tid;
        float4 v = arow[idx4];
        bool n0 = v.x != 0.f, n1 = v.y != 0.f, n2 = v.z != 0.f, n3 = v.w != 0.f;
        unsigned b0 = __ballot_sync(0xFFFFFFFFu, n0);
        unsigned b1 = __ballot_sync(0xFFFFFFFFu, n1);
        unsigned b2 = __ballot_sync(0xFFFFFFFFu, n2);
        unsigned b3 = __ballot_sync(0xFFFFFFFFu, n3);
        int tot = __popc(b0) + __popc(b1) + __popc(b2) + __popc(b3);
        int base = 0;
        if (lane == 0 && tot) base = atomicAdd(&s_cnt, tot);
        base = __shfl_sync(0xFFFFFFFFu, base, 0);
        int c0 = idx4 * 4;
        int p0 = base + __popc(b0 & ltmask);
        int p1 = base + __popc(b0) + __popc(b1 & ltmask);
        int p2 = base + __popc(b0) + __popc(b1) + __popc(b2 & ltmask);
        int p3 = base + __popc(b0) + __popc(b1) + __popc(b2) + __popc(b3 & ltmask);
        if (n0 && p0 < MAXE) s_cols[p0] = c0;
        if (n1 && p1 < MAXE) s_cols[p1] = c0 + 1;
        if (n2 && p2 < MAXE) s_cols[p2] = c0 + 2;
        if (n3 && p3 < MAXE) s_cols[p3] = c0 + 3;
    }
    __syncthreads();
    const int cnt = min(s_cnt, MAXE);

    // ---- phase 2: lrelu + scaled exp, store half p, fp32 sums ----
    const float4 f2h = g_f2v[i];
    // per-row upper bound Mhat_h = lrelu(gmaxf1_h + f2_h); fold in ln(256) scale
    float Cx, Cy, Cz, Cw;
    {
        float gx = __int_as_float(g_maxf1i[0]);
        float gy = __int_as_float(g_maxf1i[1]);
        float gz = __int_as_float(g_maxf1i[2]);
        float gw = __int_as_float(g_maxf1i[3]);
        float ax = gx + f2h.x; ax = (ax > 0.f) ? ax : 0.2f * ax;
        float ay = gy + f2h.y; ay = (ay > 0.f) ? ay : 0.2f * ay;
        float az = gz + f2h.z; az = (az > 0.f) ? az : 0.2f * az;
        float aw = gw + f2h.w; aw = (aw > 0.f) ? aw : 0.2f * aw;
        Cx = LN256 - ax; Cy = LN256 - ay; Cz = LN256 - az; Cw = LN256 - aw;
    }
    float4 sm = make_float4(0.f, 0.f, 0.f, 0.f);
    for (int e = tid; e < cnt; e += 256) {
        int j = s_cols[e];
        float4 f1 = __ldg(&g_f1v[j]);
        float sx = f1.x + f2h.x; sx = (sx > 0.f) ? sx : 0.2f * sx;
        float sy = f1.y + f2h.y; sy = (sy > 0.f) ? sy : 0.2f * sy;
        float sz = f1.z + f2h.z; sz = (sz > 0.f) ? sz : 0.2f * sz;
        float sw = f1.w + f2h.w; sw = (sw > 0.f) ? sw : 0.2f * sw;
        float px = __expf(sx + Cx), py = __expf(sy + Cy);
        float pz = __expf(sz + Cz), pw = __expf(sw + Cw);
        s_p2[e * 2]     = __float22half2_rn(make_float2(px, py));
        s_p2[e * 2 + 1] = __float22half2_rn(make_float2(pz, pw));
        sm.x += px; sm.y += py; sm.z += pz; sm.w += pw;
    }
    #pragma unroll
    for (int off = 16; off; off >>= 1) {
        sm.x += __shfl_xor_sync(0xFFFFFFFFu, sm.x, off);
        sm.y += __shfl_xor_sync(0xFFFFFFFFu, sm.y, off);
        sm.z += __shfl_xor_sync(0xFFFFFFFFu, sm.z, off);
        sm.w += __shfl_xor_sync(0xFFFFFFFFu, sm.w, off);
    }
    if (lane == 0) {
        s_red[0][warp] = sm.x; s_red[1][warp] = sm.y;
        s_red[2][warp] = sm.z; s_red[3][warp] = sm.w;
    }
    __syncthreads();
    if (tid < NHEAD) {
        float D = 0.f;
        #pragma unroll
        for (int w = 0; w < 8; w++) D += s_red[tid][w];
        s_inv[tid] = (D > 0.f) ? (1.0f / D) : 0.f;
    }
    __syncthreads();

    // ---- phase 3: 8 edge-groups x 32 threads, HFMA2 on 8 fp16 channels ----
    const int g = warp;           // edge phase 0..7
    const int t = lane;           // channels [8t, 8t+8)
    const int h = t >> 3;         // head for these channels
    const uint4* suph = (const uint4*)g_supp_h;   // row stride = 32 uint4
    const __half* sp = (const __half*)s_p2;

    float facc[8] = {};
    int e = g;
    // 8 owned edges per flush block
    for (; e + 56 < cnt; e += 64) {
        __half2 h0 = __float2half2_rn(0.f), h1 = h0, h2 = h0, h3 = h0;
        #pragma unroll
        for (int u = 0; u < 8; u++) {
            int ee = e + u * 8;
            int j = s_cols[ee];
            __half2 ph = __half2half2(sp[ee * 4 + h]);
            uint4 v = suph[j * 32 + t];
            h0 = __hfma2(ph, *(__half2*)&v.x, h0);
            h1 = __hfma2(ph, *(__half2*)&v.y, h1);
            h2 = __hfma2(ph, *(__half2*)&v.z, h2);
            h3 = __hfma2(ph, *(__half2*)&v.w, h3);
        }
        float2 f0 = __half22float2(h0), f1 = __half22float2(h1);
        float2 f2 = __half22float2(h2), f3 = __half22float2(h3);
        facc[0] += f0.x; facc[1] += f0.y; facc[2] += f1.x; facc[3] += f1.y;
        facc[4] += f2.x; facc[5] += f2.y; facc[6] += f3.x; facc[7] += f3.y;
    }
    // tail: one edge at a time, fp32 accumulate
    for (; e < cnt; e += 8) {
        int j = s_cols[e];
        float p = __half2float(sp[e * 4 + h]);
        uint4 v = suph[j * 32 + t];
        float2 f0 = __half22float2(*(__half2*)&v.x);
        float2 f1 = __half22float2(*(__half2*)&v.y);
        float2 f2 = __half22float2(*(__half2*)&v.z);
        float2 f3 = __half22float2(*(__half2*)&v.w);
        facc[0] += p * f0.x; facc[1] += p * f0.y;
        facc[2] += p * f1.x; facc[3] += p * f1.y;
        facc[4] += p * f2.x; facc[5] += p * f2.y;
        facc[6] += p * f3.x; facc[7] += p * f3.y;
    }
    #pragma unroll
    for (int k = 0; k < 8; k++) s_part[g][t][k] = facc[k];
    __syncthreads();

    // ---- phase 4: combine 8 groups, normalize, add base, store ----
    if (tid < 32) {
        const float inv = s_inv[tid >> 3];
        float r[8] = {};
        #pragma unroll
        for (int gg = 0; gg < 8; gg++)
            #pragma unroll
            for (int k = 0; k < 8; k++)
                r[k] += s_part[gg][tid][k];
        float4* o = (float4*)(out + (size_t)i * CDIM);
        float4 b0 = o[tid * 2];
        float4 b1 = o[tid * 2 + 1];
        b0.x += r[0] * inv; b0.y += r[1] * inv; b0.z += r[2] * inv; b0.w += r[3] * inv;
        b1.x += r[4] * inv; b1.y += r[5] * inv; b1.z += r[6] * inv; b1.w += r[7] * inv;
        o[tid * 2]     = b0;
        o[tid * 2 + 1] = b1;
    }
}

// ---------------- launch ----------------
extern "C" void kernel_launch(void* const* d_in, const int* in_sizes, int n_in,
                              void* d_out, int out_size) {
    const float* inputs  = (const float*)d_in[0];  // [8192,256]
    const float* adj     = (const float*)d_in[1];  // [8192,8192]
    const float* weight  = (const float*)d_in[2];  // [256,256]
    const float* wu      = (const float*)d_in[3];  // [4,64,1]
    const float* wv      = (const float*)d_in[4];  // [4,64,1]
    const float* bias    = (const float*)d_in[5];  // [1,256]
    const float* proj_w  = (const float*)d_in[6];  // [256,256]
    const float* proj_b  = (const float*)d_in[7];  // [256]
    float* out = (float*)d_out;                    // [8192,256]

    pack_b_kernel<<<(KDIM * NB) / 256, 256>>>(weight, proj_w);

    dim3 gblk(16, 16);
    dim3 ggrid(NB / 64, NROWS / 64);
    gemm_kernel<<<ggrid, gblk>>>(inputs, bias, proj_b, out);

    f1f2_kernel<<<NROWS / 8, 256>>>(wu, wv);

    attn_kernel<<<NROWS, 256>>>(adj, out);
}